// round 2
// baseline (speedup 1.0000x reference)
#include <cuda_runtime.h>
#include <math.h>

#define Mdim 2048
#define Ndim 2048
#define MP   2049
#define NP   2049
#define Bdim 4
#define Ddim 256
#define Pdim 8

__device__ float g_u[Bdim * MP];
__device__ float g_v[Bdim * NP];
__device__ float g_dA[(size_t)Bdim * MP * Pdim];
__device__ float g_dB[(size_t)Bdim * NP * Pdim];

__constant__ float c_LOG2E = 1.4426950408889634f;
#define LOG2E_ 1.4426950408889634f
#define LN2_   0.6931471805599453f

// ---------------------------------------------------------------- utilities

__device__ __forceinline__ float ex2(float x) {
    float y;
    asm("ex2.approx.f32 %0, %1;" : "=f"(y) : "f"(x));
    return y;
}

__device__ __forceinline__ float warp_reduce_sum(float x) {
#pragma unroll
    for (int o = 16; o; o >>= 1) x += __shfl_xor_sync(0xffffffffu, x, o);
    return x;
}

__device__ __forceinline__ float gelu(float x) {
    return 0.5f * x * (1.0f + erff(x * 0.7071067811865476f));
}

__device__ __forceinline__ void top5_insert(float t[5], float x) {
    if (x > t[4]) {
        t[4] = x;
#pragma unroll
        for (int i = 4; i > 0; i--) {
            float hi = fmaxf(t[i - 1], t[i]);
            float lo = fminf(t[i - 1], t[i]);
            t[i - 1] = hi;
            t[i] = lo;
        }
    }
}

__device__ __forceinline__ void top5_merge_shfl(float t[5]) {
#pragma unroll
    for (int o = 16; o; o >>= 1) {
        float p0 = __shfl_xor_sync(0xffffffffu, t[0], o);
        float p1 = __shfl_xor_sync(0xffffffffu, t[1], o);
        float p2 = __shfl_xor_sync(0xffffffffu, t[2], o);
        float p3 = __shfl_xor_sync(0xffffffffu, t[3], o);
        float p4 = __shfl_xor_sync(0xffffffffu, t[4], o);
        top5_insert(t, p0);
        top5_insert(t, p1);
        top5_insert(t, p2);
        top5_insert(t, p3);
        top5_insert(t, p4);
    }
}

// ---------------------------------------------------------------- MLP (warp-cooperative)

struct MlpW {
    float w1t[16 * 64];           // transposed: [k][u]
    float b1[64], g1[64], be1[64];
    float w2t[64 * 64];           // transposed: [k][u]
    float b2[64], g2[64], be2[64];
    float w3[64];
    float b3;
};

__device__ void load_mlp_weights(MlpW* s,
                                 const float* w1, const float* b1, const float* g1, const float* be1,
                                 const float* w2, const float* b2, const float* g2, const float* be2,
                                 const float* w3, const float* b3,
                                 int tid, int nthreads) {
    for (int i = tid; i < 16 * 64; i += nthreads) {
        int u = i / 16, k = i % 16;
        s->w1t[k * 64 + u] = w1[i];
    }
    for (int i = tid; i < 64 * 64; i += nthreads) {
        int u = i / 64, k = i % 64;
        s->w2t[k * 64 + u] = w2[i];
    }
    for (int i = tid; i < 64; i += nthreads) {
        s->b1[i] = b1[i];  s->g1[i] = g1[i];  s->be1[i] = be1[i];
        s->b2[i] = b2[i];  s->g2[i] = g2[i];  s->be2[i] = be2[i];
        s->w3[i] = w3[i];
    }
    if (tid == 0) s->b3 = b3[0];
}

// All 32 lanes must hold identical f[16]; returns mlp output to all lanes.
__device__ float warp_mlp(const MlpW* W, const float f[16], int lane) {
    float a0 = W->b1[lane], a1 = W->b1[lane + 32];
#pragma unroll
    for (int k = 0; k < 16; k++) {
        a0 = fmaf(f[k], W->w1t[k * 64 + lane], a0);
        a1 = fmaf(f[k], W->w1t[k * 64 + 32 + lane], a1);
    }
    float h0 = gelu(a0), h1 = gelu(a1);
    float mu  = warp_reduce_sum(h0 + h1) * (1.0f / 64.0f);
    float d0 = h0 - mu, d1 = h1 - mu;
    float var = warp_reduce_sum(d0 * d0 + d1 * d1) * (1.0f / 64.0f);
    float inv = 1.0f / sqrtf(var + 1e-5f);
    h0 = d0 * inv * W->g1[lane]      + W->be1[lane];
    h1 = d1 * inv * W->g1[lane + 32] + W->be1[lane + 32];

    a0 = W->b2[lane];
    a1 = W->b2[lane + 32];
#pragma unroll
    for (int k = 0; k < 32; k++) {
        float x0 = __shfl_sync(0xffffffffu, h0, k);
        float x1 = __shfl_sync(0xffffffffu, h1, k);
        a0 = fmaf(x0, W->w2t[k * 64 + lane], a0);
        a0 = fmaf(x1, W->w2t[(k + 32) * 64 + lane], a0);
        a1 = fmaf(x0, W->w2t[k * 64 + 32 + lane], a1);
        a1 = fmaf(x1, W->w2t[(k + 32) * 64 + 32 + lane], a1);
    }
    h0 = gelu(a0); h1 = gelu(a1);
    mu  = warp_reduce_sum(h0 + h1) * (1.0f / 64.0f);
    d0 = h0 - mu; d1 = h1 - mu;
    var = warp_reduce_sum(d0 * d0 + d1 * d1) * (1.0f / 64.0f);
    inv = 1.0f / sqrtf(var + 1e-5f);
    h0 = d0 * inv * W->g2[lane]      + W->be2[lane];
    h1 = d1 * inv * W->g2[lane + 32] + W->be2[lane + 32];

    float out = h0 * W->w3[lane] + h1 * W->w3[lane + 32];
    out = warp_reduce_sum(out) + W->b3;
    return out;
}

// ---------------------------------------------------------------- kernels

__global__ void init_kernel() {
    int i = blockIdx.x * 512 + threadIdx.x;
    if (i < Bdim * NP) g_v[i] = 0.0f;
    if (i < Bdim * Pdim) {
        int b = i >> 3, p = i & 7;
        g_dA[((size_t)b * MP + Mdim) * Pdim + p] = 0.0f;
        g_dB[((size_t)b * MP + Mdim) * Pdim + p] = 0.0f;
    }
}

// dOut[b,m,p] = sum_d mdesc[b,d,m] * pw[p,d] + pb[p]   (which: 0 -> g_dA, 1 -> g_dB)
__global__ __launch_bounds__(256) void proj_kernel(const float* __restrict__ mdesc,
                                                   const float* __restrict__ pw,
                                                   const float* __restrict__ pb,
                                                   int which) {
    __shared__ float sw[Pdim * Ddim];
    __shared__ float sb[Pdim];
    int tid = threadIdx.x, b = blockIdx.y;
    for (int i = tid; i < Pdim * Ddim; i += 256) sw[i] = pw[i];
    if (tid < Pdim) sb[tid] = pb[tid];
    __syncthreads();
    int m = blockIdx.x * 256 + tid;
    float acc[Pdim];
#pragma unroll
    for (int p = 0; p < Pdim; p++) acc[p] = sb[p];
    const float* base = mdesc + (size_t)b * Ddim * Mdim + m;
#pragma unroll 4
    for (int d = 0; d < Ddim; d++) {
        float val = base[(size_t)d * Mdim];
#pragma unroll
        for (int p = 0; p < Pdim; p++) acc[p] = fmaf(val, sw[p * Ddim + d], acc[p]);
    }
    float* dOut = which ? g_dB : g_dA;
    float* o = dOut + ((size_t)b * MP + m) * Pdim;
#pragma unroll
    for (int p = 0; p < Pdim; p++) o[p] = acc[p];
}

// Row phase: for each row m (incl. dustbin M), one warp streams S[m,:]+v,
// computes lse-sum + top5, then u[b,m] = u_new + MLP(feats)*log2e.
__global__ __launch_bounds__(512) void row_kernel(
    const float* __restrict__ scores, const float* __restrict__ alpha,
    const float* w1, const float* b1, const float* g1, const float* be1,
    const float* w2, const float* b2, const float* g2, const float* be2,
    const float* w3, const float* b3) {
    __shared__ MlpW W;
    __shared__ float sv[NP];
    int tid = threadIdx.x, b = blockIdx.y;
    load_mlp_weights(&W, w1, b1, g1, be1, w2, b2, g2, be2, w3, b3, tid, 512);
    for (int i = tid; i < NP; i += 512) sv[i] = g_v[b * NP + i];
    __syncthreads();

    int warp = tid >> 5, lane = tid & 31;
    int m = blockIdx.x * 16 + warp;
    if (m >= MP) return;

    float alphaL = alpha[0] * LOG2E_;
    bool dust = (m == Mdim);
    const float* srow = scores + ((size_t)b * Mdim + m) * Ndim;

    float lsum = 0.0f;
    float t[5] = {-INFINITY, -INFINITY, -INFINITY, -INFINITY, -INFINITY};

    if (!dust) {
#pragma unroll 4
        for (int k = 0; k < 64; k++) {
            int n = k * 32 + lane;
            float x = fmaf(srow[n], LOG2E_, sv[n]);
            lsum += ex2(x);
            top5_insert(t, x);
        }
    } else {
#pragma unroll 4
        for (int k = 0; k < 64; k++) {
            int n = k * 32 + lane;
            float x = alphaL + sv[n];
            lsum += ex2(x);
            top5_insert(t, x);
        }
    }
    if (lane == 0) {  // dustbin column n = N
        float x = alphaL + sv[Ndim];
        lsum += ex2(x);
        top5_insert(t, x);
    }

    float tot = warp_reduce_sum(lsum);
    top5_merge_shfl(t);
    float lse = log2f(tot);

    float l2mu = dust ? -1.0f : -12.0f;  // norm=-log2(4096)=-12; log2(N)+norm=-1
    float un = l2mu - lse;

    float f[16];
    f[0] = l2mu * LN2_;
    f[1] = un * LN2_;
    f[2] = 0.0f;
    f[3] = (t[0] - t[1]) * LN2_;
    f[4] = (t[0] - t[2]) * LN2_;
    f[5] = (t[0] - t[3]) * LN2_;
    f[6] = (t[0] - t[4]) * LN2_;
    f[7] = (l2mu - un - t[0]) * LN2_;  // spread = lse(lt) - max(lt)
    const float* da = g_dA + ((size_t)b * MP + m) * Pdim;
#pragma unroll
    for (int p = 0; p < 8; p++) f[8 + p] = da[p];

    float delta = warp_mlp(&W, f, lane);
    if (lane == 0) g_u[b * MP + m] = un + delta * LOG2E_;
}

// Column phase: block handles 32 columns, 16 warps stride rows (coalesced).
__global__ __launch_bounds__(512) void col_kernel(
    const float* __restrict__ scores, const float* __restrict__ alpha,
    const float* w1, const float* b1, const float* g1, const float* be1,
    const float* w2, const float* b2, const float* g2, const float* be2,
    const float* w3, const float* b3) {
    __shared__ MlpW W;
    __shared__ float su[MP];
    __shared__ float psum[16][32];
    __shared__ float ptop[16][32][5];
    __shared__ float sfeats[32][17];
    __shared__ float svn[32];
    int tid = threadIdx.x, b = blockIdx.y;
    load_mlp_weights(&W, w1, b1, g1, be1, w2, b2, g2, be2, w3, b3, tid, 512);
    for (int i = tid; i < MP; i += 512) su[i] = g_u[b * MP + i];
    __syncthreads();

    float alphaL = alpha[0] * LOG2E_;
    int warp = tid >> 5, lane = tid & 31;
    int col = blockIdx.x * 32 + lane;
    bool cvalid = (col < NP);
    bool cdust = (col == Ndim);

    float lsum = 0.0f;
    float t[5] = {-INFINITY, -INFINITY, -INFINITY, -INFINITY, -INFINITY};

    if (cvalid) {
        if (!cdust) {
            const float* sbase = scores + (size_t)b * Mdim * Ndim + col;
#pragma unroll 4
            for (int m = warp; m < Mdim; m += 16) {
                float x = fmaf(sbase[(size_t)m * Ndim], LOG2E_, su[m]);
                lsum += ex2(x);
                top5_insert(t, x);
            }
        } else {
            for (int m = warp; m < Mdim; m += 16) {
                float x = alphaL + su[m];
                lsum += ex2(x);
                top5_insert(t, x);
            }
        }
        if (warp == 0) {  // dustbin row m = M
            float x = alphaL + su[Mdim];
            lsum += ex2(x);
            top5_insert(t, x);
        }
    }

    psum[warp][lane] = lsum;
#pragma unroll
    for (int i = 0; i < 5; i++) ptop[warp][lane][i] = t[i];
    __syncthreads();

    if (warp == 0) {
        float tot = 0.0f;
        float tt[5] = {-INFINITY, -INFINITY, -INFINITY, -INFINITY, -INFINITY};
#pragma unroll
        for (int w = 0; w < 16; w++) {
            tot += psum[w][lane];
#pragma unroll
            for (int i = 0; i < 5; i++) top5_insert(tt, ptop[w][lane][i]);
        }
        if (cvalid) {
            float lse = log2f(tot);
            float l2nu = cdust ? -1.0f : -12.0f;
            float vn = l2nu - lse;
            sfeats[lane][0] = l2nu * LN2_;
            sfeats[lane][1] = vn * LN2_;
            sfeats[lane][2] = 0.0f;
            sfeats[lane][3] = (tt[0] - tt[1]) * LN2_;
            sfeats[lane][4] = (tt[0] - tt[2]) * LN2_;
            sfeats[lane][5] = (tt[0] - tt[3]) * LN2_;
            sfeats[lane][6] = (tt[0] - tt[4]) * LN2_;
            sfeats[lane][7] = (l2nu - vn - tt[0]) * LN2_;
            const float* db = g_dB + ((size_t)b * NP + col) * Pdim;
#pragma unroll
            for (int p = 0; p < 8; p++) sfeats[lane][8 + p] = db[p];
            svn[lane] = vn;
        }
    }
    __syncthreads();

    // 32 columns / 16 warps: each warp runs 2 MLPs
#pragma unroll
    for (int rep = 0; rep < 2; rep++) {
        int c_local = warp + rep * 16;
        int c = blockIdx.x * 32 + c_local;
        if (c < NP) {
            float f[16];
#pragma unroll
            for (int i = 0; i < 16; i++) f[i] = sfeats[c_local][i];
            float delta = warp_mlp(&W, f, lane);
            if (lane == 0) g_v[b * NP + c] = svn[c_local] + delta * LOG2E_;
        }
    }
}

// Final: out[b,m,n] = S + u + v + 12   (16 rows per block, warp per row)
__global__ __launch_bounds__(512) void out_kernel(const float* __restrict__ scores,
                                                  const float* __restrict__ alpha,
                                                  float* __restrict__ out) {
    __shared__ float sv[NP];
    int tid = threadIdx.x, b = blockIdx.y;
    for (int i = tid; i < NP; i += 512) sv[i] = g_v[b * NP + i];
    __syncthreads();
    int warp = tid >> 5, lane = tid & 31;
    int m = blockIdx.x * 16 + warp;
    if (m >= MP) return;
    float alphaL = alpha[0] * LOG2E_;
    float um = g_u[b * MP + m] + 12.0f;
    float* orow = out + ((size_t)b * MP + m) * NP;
    if (m < Mdim) {
        const float* srow = scores + ((size_t)b * Mdim + m) * Ndim;
#pragma unroll 4
        for (int k = 0; k < 64; k++) {
            int n = k * 32 + lane;
            orow[n] = fmaf(srow[n], LOG2E_, um + sv[n]);
        }
        if (lane == 0) orow[Ndim] = alphaL + um + sv[Ndim];
    } else {
        for (int k = 0; k < 65; k++) {
            int n = k * 32 + lane;
            if (n < NP) orow[n] = alphaL + um + sv[n];
        }
    }
}

// ---------------------------------------------------------------- launch

extern "C" void kernel_launch(void* const* d_in, const int* in_sizes, int n_in,
                              void* d_out, int out_size) {
    const float* scores = (const float*)d_in[0];
    const float* alpha  = (const float*)d_in[1];
    const float* mdesc0 = (const float*)d_in[2];
    const float* mdesc1 = (const float*)d_in[3];
    const float* pA_w   = (const float*)d_in[4];
    const float* pA_b   = (const float*)d_in[5];
    const float* pB_w   = (const float*)d_in[6];
    const float* pB_b   = (const float*)d_in[7];
    const float* rW[10];
    const float* cW[10];
    for (int i = 0; i < 10; i++) rW[i] = (const float*)d_in[8 + i];
    for (int i = 0; i < 10; i++) cW[i] = (const float*)d_in[18 + i];
    float* out = (float*)d_out;

    init_kernel<<<17, 512>>>();
    proj_kernel<<<dim3(Mdim / 256, Bdim), 256>>>(mdesc0, pA_w, pA_b, 0);
    proj_kernel<<<dim3(Ndim / 256, Bdim), 256>>>(mdesc1, pB_w, pB_b, 1);

    dim3 rgrid(129, Bdim);  // ceil(2049/16)
    dim3 cgrid(65, Bdim);   // ceil(2049/32)
    for (int it = 0; it < 3; it++) {
        row_kernel<<<rgrid, 512>>>(scores, alpha,
                                   rW[0], rW[1], rW[2], rW[3], rW[4],
                                   rW[5], rW[6], rW[7], rW[8], rW[9]);
        col_kernel<<<cgrid, 512>>>(scores, alpha,
                                   cW[0], cW[1], cW[2], cW[3], cW[4],
                                   cW[5], cW[6], cW[7], cW[8], cW[9]);
    }
    out_kernel<<<rgrid, 512>>>(scores, alpha, out);
}

// round 3
// speedup vs baseline: 1.0516x; 1.0516x over previous
#include <cuda_runtime.h>
#include <math.h>

#define Mdim 2048
#define Ndim 2048
#define MP   2049
#define NP   2049
#define Bdim 4
#define Ddim 256
#define Pdim 8
#define UST  2052   // padded stride for u/v (multiple of 4 -> 16B aligned slices)

__device__ float g_u[Bdim * UST];
__device__ float g_v[Bdim * UST];
__device__ float g_dA[(size_t)Bdim * MP * Pdim];
__device__ float g_dB[(size_t)Bdim * MP * Pdim];

#define LOG2E_ 1.4426950408889634f
#define LN2_   0.6931471805599453f

// ---------------------------------------------------------------- utilities

__device__ __forceinline__ float ex2(float x) {
    float y;
    asm("ex2.approx.f32 %0, %1;" : "=f"(y) : "f"(x));
    return y;
}

__device__ __forceinline__ float warp_reduce_sum(float x) {
#pragma unroll
    for (int o = 16; o; o >>= 1) x += __shfl_xor_sync(0xffffffffu, x, o);
    return x;
}

__device__ __forceinline__ float gelu(float x) {
    return 0.5f * x * (1.0f + erff(x * 0.7071067811865476f));
}

__device__ __forceinline__ void top5_insert(float t[5], float x) {
    if (x > t[4]) {
        t[4] = x;
#pragma unroll
        for (int i = 4; i > 0; i--) {
            float hi = fmaxf(t[i - 1], t[i]);
            float lo = fminf(t[i - 1], t[i]);
            t[i - 1] = hi;
            t[i] = lo;
        }
    }
}

__device__ __forceinline__ void top5_merge_shfl(float t[5]) {
#pragma unroll
    for (int o = 16; o; o >>= 1) {
        float p0 = __shfl_xor_sync(0xffffffffu, t[0], o);
        float p1 = __shfl_xor_sync(0xffffffffu, t[1], o);
        float p2 = __shfl_xor_sync(0xffffffffu, t[2], o);
        float p3 = __shfl_xor_sync(0xffffffffu, t[3], o);
        float p4 = __shfl_xor_sync(0xffffffffu, t[4], o);
        top5_insert(t, p0);
        top5_insert(t, p1);
        top5_insert(t, p2);
        top5_insert(t, p3);
        top5_insert(t, p4);
    }
}

// ---------------------------------------------------------------- MLP (warp-cooperative)

struct MlpW {
    float w1t[16 * 64];
    float b1[64], g1[64], be1[64];
    float w2t[64 * 64];
    float b2[64], g2[64], be2[64];
    float w3[64];
    float b3;
};

__device__ void load_mlp_weights(MlpW* s,
                                 const float* w1, const float* b1, const float* g1, const float* be1,
                                 const float* w2, const float* b2, const float* g2, const float* be2,
                                 const float* w3, const float* b3,
                                 int tid, int nthreads) {
    for (int i = tid; i < 16 * 64; i += nthreads) {
        int u = i / 16, k = i % 16;
        s->w1t[k * 64 + u] = w1[i];
    }
    for (int i = tid; i < 64 * 64; i += nthreads) {
        int u = i / 64, k = i % 64;
        s->w2t[k * 64 + u] = w2[i];
    }
    for (int i = tid; i < 64; i += nthreads) {
        s->b1[i] = b1[i];  s->g1[i] = g1[i];  s->be1[i] = be1[i];
        s->b2[i] = b2[i];  s->g2[i] = g2[i];  s->be2[i] = be2[i];
        s->w3[i] = w3[i];
    }
    if (tid == 0) s->b3 = b3[0];
}

__device__ float warp_mlp(const MlpW* W, const float f[16], int lane) {
    float a0 = W->b1[lane], a1 = W->b1[lane + 32];
#pragma unroll
    for (int k = 0; k < 16; k++) {
        a0 = fmaf(f[k], W->w1t[k * 64 + lane], a0);
        a1 = fmaf(f[k], W->w1t[k * 64 + 32 + lane], a1);
    }
    float h0 = gelu(a0), h1 = gelu(a1);
    float mu  = warp_reduce_sum(h0 + h1) * (1.0f / 64.0f);
    float d0 = h0 - mu, d1 = h1 - mu;
    float var = warp_reduce_sum(d0 * d0 + d1 * d1) * (1.0f / 64.0f);
    float inv = 1.0f / sqrtf(var + 1e-5f);
    h0 = d0 * inv * W->g1[lane]      + W->be1[lane];
    h1 = d1 * inv * W->g1[lane + 32] + W->be1[lane + 32];

    a0 = W->b2[lane];
    a1 = W->b2[lane + 32];
#pragma unroll
    for (int k = 0; k < 32; k++) {
        float x0 = __shfl_sync(0xffffffffu, h0, k);
        float x1 = __shfl_sync(0xffffffffu, h1, k);
        a0 = fmaf(x0, W->w2t[k * 64 + lane], a0);
        a0 = fmaf(x1, W->w2t[(k + 32) * 64 + lane], a0);
        a1 = fmaf(x0, W->w2t[k * 64 + 32 + lane], a1);
        a1 = fmaf(x1, W->w2t[(k + 32) * 64 + 32 + lane], a1);
    }
    h0 = gelu(a0); h1 = gelu(a1);
    mu  = warp_reduce_sum(h0 + h1) * (1.0f / 64.0f);
    d0 = h0 - mu; d1 = h1 - mu;
    var = warp_reduce_sum(d0 * d0 + d1 * d1) * (1.0f / 64.0f);
    inv = 1.0f / sqrtf(var + 1e-5f);
    h0 = d0 * inv * W->g2[lane]      + W->be2[lane];
    h1 = d1 * inv * W->g2[lane + 32] + W->be2[lane + 32];

    float out = h0 * W->w3[lane] + h1 * W->w3[lane + 32];
    out = warp_reduce_sum(out) + W->b3;
    return out;
}

// ---------------------------------------------------------------- kernels

__global__ void init_kernel() {
    int i = blockIdx.x * 512 + threadIdx.x;
    if (i < Bdim * UST) g_v[i] = 0.0f;
    if (i < Bdim * Pdim) {
        int b = i >> 3, p = i & 7;
        g_dA[((size_t)b * MP + Mdim) * Pdim + p] = 0.0f;
        g_dB[((size_t)b * MP + Mdim) * Pdim + p] = 0.0f;
    }
}

__global__ __launch_bounds__(256) void proj_kernel(const float* __restrict__ mdesc,
                                                   const float* __restrict__ pw,
                                                   const float* __restrict__ pb,
                                                   int which) {
    __shared__ float sw[Pdim * Ddim];
    __shared__ float sb[Pdim];
    int tid = threadIdx.x, b = blockIdx.y;
    for (int i = tid; i < Pdim * Ddim; i += 256) sw[i] = pw[i];
    if (tid < Pdim) sb[tid] = pb[tid];
    __syncthreads();
    int m = blockIdx.x * 256 + tid;
    float acc[Pdim];
#pragma unroll
    for (int p = 0; p < Pdim; p++) acc[p] = sb[p];
    const float* base = mdesc + (size_t)b * Ddim * Mdim + m;
#pragma unroll 4
    for (int d = 0; d < Ddim; d++) {
        float val = base[(size_t)d * Mdim];
#pragma unroll
        for (int p = 0; p < Pdim; p++) acc[p] = fmaf(val, sw[p * Ddim + d], acc[p]);
    }
    float* dOut = which ? g_dB : g_dA;
    float* o = dOut + ((size_t)b * MP + m) * Pdim;
#pragma unroll
    for (int p = 0; p < Pdim; p++) o[p] = acc[p];
}

// Row phase: warp per row; float4 streaming of scores + v.
__global__ __launch_bounds__(512) void row_kernel(
    const float* __restrict__ scores, const float* __restrict__ alpha,
    const float* w1, const float* b1, const float* g1, const float* be1,
    const float* w2, const float* b2, const float* g2, const float* be2,
    const float* w3, const float* b3) {
    __shared__ MlpW W;
    __shared__ __align__(16) float svs[UST];
    int tid = threadIdx.x, b = blockIdx.y;
    load_mlp_weights(&W, w1, b1, g1, be1, w2, b2, g2, be2, w3, b3, tid, 512);
    {
        const float4* gv4 = reinterpret_cast<const float4*>(g_v + b * UST);
        float4* sv4w = reinterpret_cast<float4*>(svs);
        for (int i = tid; i < UST / 4; i += 512) sv4w[i] = gv4[i];
    }
    __syncthreads();

    int warp = tid >> 5, lane = tid & 31;
    int m = blockIdx.x * 16 + warp;
    if (m >= MP) return;

    float alphaL = alpha[0] * LOG2E_;
    bool dust = (m == Mdim);
    const float4* srow4 = reinterpret_cast<const float4*>(scores + ((size_t)b * Mdim + m) * Ndim);
    const float4* sv4 = reinterpret_cast<const float4*>(svs);

    float s0 = 0.0f, s1 = 0.0f, s2 = 0.0f, s3 = 0.0f;
    float t[5] = {-INFINITY, -INFINITY, -INFINITY, -INFINITY, -INFINITY};

    if (!dust) {
#pragma unroll 4
        for (int k = 0; k < 16; k++) {
            float4 s = srow4[k * 32 + lane];
            float4 vv = sv4[k * 32 + lane];
            float x0 = fmaf(s.x, LOG2E_, vv.x);
            float x1 = fmaf(s.y, LOG2E_, vv.y);
            float x2 = fmaf(s.z, LOG2E_, vv.z);
            float x3 = fmaf(s.w, LOG2E_, vv.w);
            s0 += ex2(x0); s1 += ex2(x1); s2 += ex2(x2); s3 += ex2(x3);
            top5_insert(t, x0); top5_insert(t, x1);
            top5_insert(t, x2); top5_insert(t, x3);
        }
    } else {
#pragma unroll 4
        for (int k = 0; k < 16; k++) {
            float4 vv = sv4[k * 32 + lane];
            float x0 = alphaL + vv.x;
            float x1 = alphaL + vv.y;
            float x2 = alphaL + vv.z;
            float x3 = alphaL + vv.w;
            s0 += ex2(x0); s1 += ex2(x1); s2 += ex2(x2); s3 += ex2(x3);
            top5_insert(t, x0); top5_insert(t, x1);
            top5_insert(t, x2); top5_insert(t, x3);
        }
    }
    if (lane == 0) {  // dustbin column n = N
        float x = alphaL + svs[Ndim];
        s0 += ex2(x);
        top5_insert(t, x);
    }

    float tot = warp_reduce_sum((s0 + s1) + (s2 + s3));
    top5_merge_shfl(t);
    float lse = log2f(tot);

    float l2mu = dust ? -1.0f : -12.0f;
    float un = l2mu - lse;

    float f[16];
    f[0] = l2mu * LN2_;
    f[1] = un * LN2_;
    f[2] = 0.0f;
    f[3] = (t[0] - t[1]) * LN2_;
    f[4] = (t[0] - t[2]) * LN2_;
    f[5] = (t[0] - t[3]) * LN2_;
    f[6] = (t[0] - t[4]) * LN2_;
    f[7] = (l2mu - un - t[0]) * LN2_;
    const float* da = g_dA + ((size_t)b * MP + m) * Pdim;
#pragma unroll
    for (int p = 0; p < 8; p++) f[8 + p] = da[p];

    float delta = warp_mlp(&W, f, lane);
    if (lane == 0) g_u[b * UST + m] = un + delta * LOG2E_;
}

// Column phase: block handles 32 columns, 16 warps stride rows (coalesced).
// On the final iteration (out != nullptr) also writes the output matrix.
__global__ __launch_bounds__(512) void col_kernel(
    const float* __restrict__ scores, const float* __restrict__ alpha,
    const float* w1, const float* b1, const float* g1, const float* be1,
    const float* w2, const float* b2, const float* g2, const float* be2,
    const float* w3, const float* b3,
    float* __restrict__ out) {
    __shared__ MlpW W;
    __shared__ float su[MP];
    __shared__ float psum[16][32];
    __shared__ float ptop[16][32][5];
    __shared__ float sfeats[32][17];
    __shared__ float svn[32];
    __shared__ float svfin[32];
    int tid = threadIdx.x, b = blockIdx.y;
    load_mlp_weights(&W, w1, b1, g1, be1, w2, b2, g2, be2, w3, b3, tid, 512);
    for (int i = tid; i < MP; i += 512) su[i] = g_u[b * UST + i];
    __syncthreads();

    float alphaL = alpha[0] * LOG2E_;
    int warp = tid >> 5, lane = tid & 31;
    int col = blockIdx.x * 32 + lane;
    bool cvalid = (col < NP);
    bool cdust = (col == Ndim);

    float a0 = 0.0f, a1 = 0.0f;
    float t[5] = {-INFINITY, -INFINITY, -INFINITY, -INFINITY, -INFINITY};

    if (cvalid) {
        if (!cdust) {
            const float* p = scores + (size_t)b * Mdim * Ndim + (size_t)warp * Ndim + col;
#pragma unroll 8
            for (int i = 0; i < 128; i++) {
                int m = warp + 16 * i;
                float x = fmaf(p[(size_t)(16 * i) * Ndim], LOG2E_, su[m]);
                if (i & 1) a1 += ex2(x); else a0 += ex2(x);
                top5_insert(t, x);
            }
        } else {
#pragma unroll 8
            for (int i = 0; i < 128; i++) {
                int m = warp + 16 * i;
                float x = alphaL + su[m];
                if (i & 1) a1 += ex2(x); else a0 += ex2(x);
                top5_insert(t, x);
            }
        }
        if (warp == 0) {  // dustbin row m = M
            float x = alphaL + su[Mdim];
            a0 += ex2(x);
            top5_insert(t, x);
        }
    }

    psum[warp][lane] = a0 + a1;
#pragma unroll
    for (int i = 0; i < 5; i++) ptop[warp][lane][i] = t[i];
    __syncthreads();

    if (warp == 0) {
        float tot = 0.0f;
        float tt[5] = {-INFINITY, -INFINITY, -INFINITY, -INFINITY, -INFINITY};
#pragma unroll
        for (int w = 0; w < 16; w++) {
            tot += psum[w][lane];
#pragma unroll
            for (int i = 0; i < 5; i++) top5_insert(tt, ptop[w][lane][i]);
        }
        if (cvalid) {
            float lse = log2f(tot);
            float l2nu = cdust ? -1.0f : -12.0f;
            float vn = l2nu - lse;
            sfeats[lane][0] = l2nu * LN2_;
            sfeats[lane][1] = vn * LN2_;
            sfeats[lane][2] = 0.0f;
            sfeats[lane][3] = (tt[0] - tt[1]) * LN2_;
            sfeats[lane][4] = (tt[0] - tt[2]) * LN2_;
            sfeats[lane][5] = (tt[0] - tt[3]) * LN2_;
            sfeats[lane][6] = (tt[0] - tt[4]) * LN2_;
            sfeats[lane][7] = (l2nu - vn - tt[0]) * LN2_;
            const float* db = g_dB + ((size_t)b * MP + col) * Pdim;
#pragma unroll
            for (int p = 0; p < 8; p++) sfeats[lane][8 + p] = db[p];
            svn[lane] = vn;
        }
    }
    __syncthreads();

#pragma unroll
    for (int rep = 0; rep < 2; rep++) {
        int c_local = warp + rep * 16;
        int c = blockIdx.x * 32 + c_local;
        if (c < NP) {
            float f[16];
#pragma unroll
            for (int i = 0; i < 16; i++) f[i] = sfeats[c_local][i];
            float delta = warp_mlp(&W, f, lane);
            if (lane == 0) {
                float vfin = svn[c_local] + delta * LOG2E_;
                g_v[b * UST + c] = vfin;
                svfin[c_local] = vfin;
            }
        }
    }

    if (out != nullptr) {
        __syncthreads();
        if (cvalid) {
            float vc = svfin[lane] + 12.0f;  // v + (-norm)
            float* obase = out + (size_t)b * MP * NP + col;
            if (!cdust) {
                const float* p = scores + (size_t)b * Mdim * Ndim + (size_t)warp * Ndim + col;
#pragma unroll 8
                for (int i = 0; i < 128; i++) {
                    int m = warp + 16 * i;
                    obase[(size_t)m * NP] = fmaf(p[(size_t)(16 * i) * Ndim], LOG2E_, su[m] + vc);
                }
            } else {
#pragma unroll 8
                for (int i = 0; i < 128; i++) {
                    int m = warp + 16 * i;
                    obase[(size_t)m * NP] = alphaL + su[m] + vc;
                }
            }
            if (warp == 0) obase[(size_t)Mdim * NP] = alphaL + su[Mdim] + vc;
        }
    }
}

// ---------------------------------------------------------------- launch

extern "C" void kernel_launch(void* const* d_in, const int* in_sizes, int n_in,
                              void* d_out, int out_size) {
    const float* scores = (const float*)d_in[0];
    const float* alpha  = (const float*)d_in[1];
    const float* mdesc0 = (const float*)d_in[2];
    const float* mdesc1 = (const float*)d_in[3];
    const float* pA_w   = (const float*)d_in[4];
    const float* pA_b   = (const float*)d_in[5];
    const float* pB_w   = (const float*)d_in[6];
    const float* pB_b   = (const float*)d_in[7];
    const float* rW[10];
    const float* cW[10];
    for (int i = 0; i < 10; i++) rW[i] = (const float*)d_in[8 + i];
    for (int i = 0; i < 10; i++) cW[i] = (const float*)d_in[18 + i];
    float* out = (float*)d_out;

    init_kernel<<<17, 512>>>();
    proj_kernel<<<dim3(Mdim / 256, Bdim), 256>>>(mdesc0, pA_w, pA_b, 0);
    proj_kernel<<<dim3(Ndim / 256, Bdim), 256>>>(mdesc1, pB_w, pB_b, 1);

    dim3 rgrid(129, Bdim);  // ceil(2049/16)
    dim3 cgrid(65, Bdim);   // ceil(2049/32)
    for (int it = 0; it < 3; it++) {
        row_kernel<<<rgrid, 512>>>(scores, alpha,
                                   rW[0], rW[1], rW[2], rW[3], rW[4],
                                   rW[5], rW[6], rW[7], rW[8], rW[9]);
        col_kernel<<<cgrid, 512>>>(scores, alpha,
                                   cW[0], cW[1], cW[2], cW[3], cW[4],
                                   cW[5], cW[6], cW[7], cW[8], cW[9],
                                   (it == 2) ? out : nullptr);
    }
}